// round 1
// baseline (speedup 1.0000x reference)
#include <cuda_runtime.h>
#include <math.h>

// Problem constants
#define HID   1024
#define NH    16
#define DH    64
#define SEQ   4096
#define BATCH 2
#define WIN   512
#define MTOT  (BATCH*SEQ)   // 8192 tokens

// Scratch buffers (allocation-free rule: __device__ globals)
__device__ float g_Q[(size_t)MTOT*HID];  // layout [b,h,s,d]
__device__ float g_K[(size_t)MTOT*HID];  // layout [b,h,s,d]
__device__ float g_V[(size_t)MTOT*HID];  // layout [b,h,s,d]
__device__ float g_A[(size_t)MTOT*HID];  // layout [b,s,h*d] == [token, HID]

// ---------------------------------------------------------------------------
// NT GEMM: C[m,n] = sum_k A[m,k] * W[n,k]   (nn.Linear: x @ W.T)
// 128x128 tile, BK=16, 256 threads, 8x8 register micro-tile.
// ---------------------------------------------------------------------------
#define BM 128
#define BN 128
#define BK 16

template <bool PERMUTE>
__device__ __forceinline__ void gemm_body(const float* __restrict__ A,
                                          const float* __restrict__ W,
                                          float* __restrict__ C)
{
    __shared__ float As[BK][BM];
    __shared__ float Bs[BK][BN];

    const int tid = threadIdx.x;
    const int m0  = blockIdx.x * BM;
    const int n0  = blockIdx.y * BN;

    // global->shared load mapping: 256 threads, each loads 2 rows x 1 float4
    const int lrow = tid >> 2;          // 0..63
    const int lk   = (tid & 3) << 2;    // 0,4,8,12

    // compute mapping: 16x16 thread grid, 8x8 micro-tile
    const int ty = tid >> 4;            // 0..15 -> rows
    const int tx = tid & 15;            // 0..15 -> cols

    float acc[8][8];
#pragma unroll
    for (int i = 0; i < 8; i++)
#pragma unroll
        for (int j = 0; j < 8; j++) acc[i][j] = 0.0f;

    for (int k0 = 0; k0 < HID; k0 += BK) {
#pragma unroll
        for (int r = 0; r < 2; r++) {
            const int row = lrow + r * 64;
            float4 a = *(const float4*)(A + (size_t)(m0 + row) * HID + k0 + lk);
            As[lk + 0][row] = a.x;
            As[lk + 1][row] = a.y;
            As[lk + 2][row] = a.z;
            As[lk + 3][row] = a.w;
            float4 bv = *(const float4*)(W + (size_t)(n0 + row) * HID + k0 + lk);
            Bs[lk + 0][row] = bv.x;
            Bs[lk + 1][row] = bv.y;
            Bs[lk + 2][row] = bv.z;
            Bs[lk + 3][row] = bv.w;
        }
        __syncthreads();

#pragma unroll
        for (int kk = 0; kk < BK; kk++) {
            float ar[8], br[8];
            *(float4*)&ar[0] = *(const float4*)&As[kk][ty * 8];
            *(float4*)&ar[4] = *(const float4*)&As[kk][ty * 8 + 4];
            *(float4*)&br[0] = *(const float4*)&Bs[kk][tx * 8];
            *(float4*)&br[4] = *(const float4*)&Bs[kk][tx * 8 + 4];
#pragma unroll
            for (int i = 0; i < 8; i++)
#pragma unroll
                for (int j = 0; j < 8; j++)
                    acc[i][j] = fmaf(ar[i], br[j], acc[i][j]);
        }
        __syncthreads();
    }

    if (!PERMUTE) {
#pragma unroll
        for (int i = 0; i < 8; i++) {
            const int m = m0 + ty * 8 + i;
            float* cp = C + (size_t)m * HID + n0 + tx * 8;
            *(float4*)cp       = make_float4(acc[i][0], acc[i][1], acc[i][2], acc[i][3]);
            *(float4*)(cp + 4) = make_float4(acc[i][4], acc[i][5], acc[i][6], acc[i][7]);
        }
    } else {
        // write to [b,h,s,d] layout
        const int n = n0 + tx * 8;      // 8 consecutive cols, same head (8 | 64)
        const int h = n >> 6;
        const int d = n & 63;
#pragma unroll
        for (int i = 0; i < 8; i++) {
            const int m = m0 + ty * 8 + i;
            const int b = m >> 12;          // /SEQ
            const int s = m & (SEQ - 1);
            float* cp = C + (((size_t)(b * NH + h) * SEQ + s) * DH) + d;
            *(float4*)cp       = make_float4(acc[i][0], acc[i][1], acc[i][2], acc[i][3]);
            *(float4*)(cp + 4) = make_float4(acc[i][4], acc[i][5], acc[i][6], acc[i][7]);
        }
    }
}

__global__ __launch_bounds__(256)
void qkv_kernel(const float* __restrict__ x,
                const float* __restrict__ Wq,
                const float* __restrict__ Wk,
                const float* __restrict__ Wv)
{
    const float* W;
    float* C;
    if (blockIdx.z == 0)      { W = Wq; C = g_Q; }
    else if (blockIdx.z == 1) { W = Wk; C = g_K; }
    else                      { W = Wv; C = g_V; }
    gemm_body<true>(x, W, C);
}

__global__ __launch_bounds__(256)
void oproj_kernel(const float* __restrict__ Wo, float* __restrict__ out)
{
    gemm_body<false>(g_A, Wo, out);
}

// ---------------------------------------------------------------------------
// Sliding-window causal attention.
// One block = (64 queries, one head, one batch). One thread per query.
// K/V chunks of 64 keys staged in SMEM; all threads walk the same key j
// simultaneously -> SMEM broadcast reads. Online softmax.
// ---------------------------------------------------------------------------
__global__ __launch_bounds__(64)
void attn_kernel(const int* __restrict__ attn_mask)
{
    const int qb = blockIdx.x;          // query chunk, 0..63
    const int h  = blockIdx.y;
    const int b  = blockIdx.z;
    const int tid = threadIdx.x;        // 0..63
    const int q  = qb * 64 + tid;       // global query position in sequence

    const float* __restrict__ Qh = g_Q + (size_t)(b * NH + h) * SEQ * DH;
    const float* __restrict__ Kh = g_K + (size_t)(b * NH + h) * SEQ * DH;
    const float* __restrict__ Vh = g_V + (size_t)(b * NH + h) * SEQ * DH;

    __shared__ float Ks[64 * DH];
    __shared__ float Vs[64 * DH];
    __shared__ int   msk[64];

    // load this thread's query row into registers
    float qv[DH];
    {
        const float4* qp = (const float4*)(Qh + (size_t)q * DH);
#pragma unroll
        for (int i = 0; i < DH / 4; i++) {
            float4 f = qp[i];
            qv[i * 4 + 0] = f.x; qv[i * 4 + 1] = f.y;
            qv[i * 4 + 2] = f.z; qv[i * 4 + 3] = f.w;
        }
    }

    float mrun = -INFINITY;
    float lrun = 0.0f;
    float o[DH];
#pragma unroll
    for (int d = 0; d < DH; d++) o[d] = 0.0f;

    const int c_lo = (qb >= 8) ? (qb - 8) : 0;   // window reach: 512 = 8 chunks

    for (int c = c_lo; c <= qb; c++) {
        // cooperative coalesced load of K/V chunk (64x64 each)
        const float4* Ksrc = (const float4*)(Kh + (size_t)c * 64 * DH);
        const float4* Vsrc = (const float4*)(Vh + (size_t)c * 64 * DH);
        float4* Kd = (float4*)Ks;
        float4* Vd = (float4*)Vs;
#pragma unroll
        for (int i = 0; i < 16; i++) {
            Kd[tid + i * 64] = Ksrc[tid + i * 64];
            Vd[tid + i * 64] = Vsrc[tid + i * 64];
        }
        msk[tid] = attn_mask[b * SEQ + c * 64 + tid];
        __syncthreads();

        const int jj0 = c * 64;
        for (int j = 0; j < 64; j++) {
            const int jj = jj0 + j;
            const bool valid = (jj <= q) && (jj >= q - (WIN - 1)) && (msk[j] != 0);
            if (valid) {
                // dot(q, k_j) — broadcast SMEM reads
                const float4* kr = (const float4*)&Ks[j * DH];
                float s = 0.0f;
#pragma unroll
                for (int d4 = 0; d4 < DH / 4; d4++) {
                    float4 kk4 = kr[d4];
                    s = fmaf(qv[d4 * 4 + 0], kk4.x, s);
                    s = fmaf(qv[d4 * 4 + 1], kk4.y, s);
                    s = fmaf(qv[d4 * 4 + 2], kk4.z, s);
                    s = fmaf(qv[d4 * 4 + 3], kk4.w, s);
                }
                s *= 0.125f;   // 1/sqrt(64)

                if (s > mrun) {
                    const float corr = __expf(mrun - s);   // exp(-inf)=0 on first hit
                    lrun *= corr;
#pragma unroll
                    for (int d = 0; d < DH; d++) o[d] *= corr;
                    mrun = s;
                }
                const float p = __expf(s - mrun);
                lrun += p;
                const float4* vr = (const float4*)&Vs[j * DH];
#pragma unroll
                for (int d4 = 0; d4 < DH / 4; d4++) {
                    float4 vv4 = vr[d4];
                    o[d4 * 4 + 0] = fmaf(p, vv4.x, o[d4 * 4 + 0]);
                    o[d4 * 4 + 1] = fmaf(p, vv4.y, o[d4 * 4 + 1]);
                    o[d4 * 4 + 2] = fmaf(p, vv4.z, o[d4 * 4 + 2]);
                    o[d4 * 4 + 3] = fmaf(p, vv4.w, o[d4 * 4 + 3]);
                }
            }
        }
        __syncthreads();
    }

    // normalize and write to token-major [m, HID] layout for the O-projection
    const float inv = 1.0f / lrun;
    float* op = g_A + ((size_t)(b * SEQ) + q) * HID + h * DH;
#pragma unroll
    for (int d4 = 0; d4 < DH / 4; d4++) {
        float4 f;
        f.x = o[d4 * 4 + 0] * inv;
        f.y = o[d4 * 4 + 1] * inv;
        f.z = o[d4 * 4 + 2] * inv;
        f.w = o[d4 * 4 + 3] * inv;
        *(float4*)(op + d4 * 4) = f;
    }
}

// ---------------------------------------------------------------------------
// Launch
// ---------------------------------------------------------------------------
extern "C" void kernel_launch(void* const* d_in, const int* in_sizes, int n_in,
                              void* d_out, int out_size)
{
    const float* x    = (const float*)d_in[0];
    const int*   mask = (const int*)  d_in[1];
    const float* Wq   = (const float*)d_in[2];
    const float* Wk   = (const float*)d_in[3];
    const float* Wv   = (const float*)d_in[4];
    const float* Wo   = (const float*)d_in[5];
    float* out = (float*)d_out;

    dim3 ggrid(MTOT / BM, HID / BN, 3);
    qkv_kernel<<<ggrid, 256>>>(x, Wq, Wk, Wv);

    dim3 agrid(SEQ / 64, NH, BATCH);
    attn_kernel<<<agrid, 64>>>(mask);

    dim3 ogrid(MTOT / BM, HID / BN, 1);
    oproj_kernel<<<ogrid, 256>>>(Wo, out);
}

// round 3
// speedup vs baseline: 1.6386x; 1.6386x over previous
#include <cuda_runtime.h>
#include <cuda_bf16.h>
#include <math.h>
#include <stdint.h>

// Problem constants
#define HID   1024
#define NH    16
#define DH    64
#define SEQ   4096
#define BATCH 2
#define WIN   512
#define MTOT  (BATCH*SEQ)          // 8192 tokens
#define XELEMS ((size_t)MTOT*HID)  // 8M
#define WELEMS ((size_t)HID*HID)   // 1M

// ---------------------------------------------------------------------------
// Scratch (__device__ globals; no allocations allowed)
// ---------------------------------------------------------------------------
__device__ __nv_bfloat16 g_Xhi[XELEMS];
__device__ __nv_bfloat16 g_Xlo[XELEMS];
__device__ __nv_bfloat16 g_Whi[4 * WELEMS];   // q,k,v,o
__device__ __nv_bfloat16 g_Wlo[4 * WELEMS];
__device__ float g_Q[XELEMS];                 // [b,h,s,d]
__device__ float g_K[XELEMS];
__device__ float g_V[XELEMS];
__device__ __nv_bfloat16 g_Ahi[XELEMS];       // attn out, [token, HID] split
__device__ __nv_bfloat16 g_Alo[XELEMS];

// ---------------------------------------------------------------------------
// PTX helpers (baseline PTX only — no sm_103a-specific instructions!)
// ---------------------------------------------------------------------------
__device__ __forceinline__ uint32_t smem_u32(const void* p) {
    uint32_t a;
    asm("{ .reg .u64 t; cvta.to.shared.u64 t, %1; cvt.u32.u64 %0, t; }" : "=r"(a) : "l"(p));
    return a;
}
__device__ __forceinline__ void cp16(uint32_t dst, const void* src) {
    asm volatile("cp.async.cg.shared.global [%0], [%1], 16;" :: "r"(dst), "l"(src));
}
#define CP_COMMIT() asm volatile("cp.async.commit_group;" ::: "memory")
template <int N>
__device__ __forceinline__ void cp_wait() {
    asm volatile("cp.async.wait_group %0;" :: "n"(N) : "memory");
}
__device__ __forceinline__ void ldsm_x4(uint32_t& r0, uint32_t& r1, uint32_t& r2, uint32_t& r3, uint32_t a) {
    asm volatile("ldmatrix.sync.aligned.m8n8.x4.shared.b16 {%0,%1,%2,%3}, [%4];"
                 : "=r"(r0), "=r"(r1), "=r"(r2), "=r"(r3) : "r"(a));
}
__device__ __forceinline__ void mma16816(float* c, const uint32_t* a, const uint32_t* b) {
    asm volatile(
        "mma.sync.aligned.m16n8k16.row.col.f32.bf16.bf16.f32 "
        "{%0,%1,%2,%3}, {%4,%5,%6,%7}, {%8,%9}, {%0,%1,%2,%3};"
        : "+f"(c[0]), "+f"(c[1]), "+f"(c[2]), "+f"(c[3])
        : "r"(a[0]), "r"(a[1]), "r"(a[2]), "r"(a[3]), "r"(b[0]), "r"(b[1]));
}

// ---------------------------------------------------------------------------
// fp32 -> bf16 hi/lo split of x and the 4 weight matrices
// ---------------------------------------------------------------------------
__global__ __launch_bounds__(256)
void split_kernel(const float* __restrict__ x,
                  const float* __restrict__ Wq, const float* __restrict__ Wk,
                  const float* __restrict__ Wv, const float* __restrict__ Wo)
{
    size_t t = (size_t)blockIdx.x * 256 + threadIdx.x;
    size_t e = t * 4;
    const float* src;
    __nv_bfloat16 *dh, *dl;
    if (e < XELEMS) {
        src = x + e; dh = g_Xhi + e; dl = g_Xlo + e;
    } else {
        size_t r = e - XELEMS;
        int w = (int)(r >> 20);
        size_t off = r & (WELEMS - 1);
        const float* Ws[4] = {Wq, Wk, Wv, Wo};
        src = Ws[w] + off;
        dh = g_Whi + (size_t)w * WELEMS + off;
        dl = g_Wlo + (size_t)w * WELEMS + off;
    }
    float4 v = *(const float4*)src;
    __nv_bfloat16 h0 = __float2bfloat16(v.x), h1 = __float2bfloat16(v.y);
    __nv_bfloat16 h2 = __float2bfloat16(v.z), h3 = __float2bfloat16(v.w);
    ushort4 uh, ul;
    uh.x = __bfloat16_as_ushort(h0); uh.y = __bfloat16_as_ushort(h1);
    uh.z = __bfloat16_as_ushort(h2); uh.w = __bfloat16_as_ushort(h3);
    ul.x = __bfloat16_as_ushort(__float2bfloat16(v.x - __bfloat162float(h0)));
    ul.y = __bfloat16_as_ushort(__float2bfloat16(v.y - __bfloat162float(h1)));
    ul.z = __bfloat16_as_ushort(__float2bfloat16(v.z - __bfloat162float(h2)));
    ul.w = __bfloat16_as_ushort(__float2bfloat16(v.w - __bfloat162float(h3)));
    *(ushort4*)dh = uh;
    *(ushort4*)dl = ul;
}

// ---------------------------------------------------------------------------
// bf16-split GEMM via mma.sync (HMMA): C[m,n] = sum_k A[m,k]*W[n,k]
// C ≈ Ahi*Whi + Ahi*Wlo + Alo*Whi, fp32 accumulate.
// Tile 128x128, BK=32, 256 threads (8 warps, 2x4), warp tile 64x32.
// Double-buffered cp.async. SMEM rows padded to 80B (conflict-free ldmatrix).
// ---------------------------------------------------------------------------
#define BM 128
#define BN 128
#define BK 32
#define RSB 80                       // bytes per smem row (32 bf16 + 16B pad)
#define TSB (128 * RSB)              // 10240 bytes per tile
#define BUFB (4 * TSB)               // 40960 per buffer (Ahi,Alo,Bhi,Blo)
#define GSMEM (2 * BUFB)             // 81920
#define NCH (HID / BK)               // 32

__device__ __forceinline__ void load_chunk(
    uint32_t sbuf, int tid,
    const __nv_bfloat16* __restrict__ Ahi, const __nv_bfloat16* __restrict__ Alo,
    const __nv_bfloat16* __restrict__ Bhi, const __nv_bfloat16* __restrict__ Blo,
    int m0, int n0, int k0)
{
#pragma unroll
    for (int i = 0; i < 8; i++) {
        const int tile = i >> 1;                 // compile-time
        const int idx = tid + (i & 1) * 256;     // 0..511
        const int r = idx >> 2;
        const int c = idx & 3;
        const __nv_bfloat16* base =
            (tile == 0) ? Ahi : (tile == 1) ? Alo : (tile == 2) ? Bhi : Blo;
        const int row0 = (tile < 2) ? m0 : n0;
        const __nv_bfloat16* src = base + (size_t)(row0 + r) * HID + k0 + c * 8;
        cp16(sbuf + tile * TSB + r * RSB + c * 16, src);
    }
}

template <int PERM>
__device__ __forceinline__ void gemm_body(
    const __nv_bfloat16* __restrict__ Ahi, const __nv_bfloat16* __restrict__ Alo,
    const __nv_bfloat16* __restrict__ Bhi, const __nv_bfloat16* __restrict__ Blo,
    float* __restrict__ C)
{
    extern __shared__ char smem[];
    const uint32_t sb = smem_u32(smem);
    const int tid = threadIdx.x;
    const int lane = tid & 31;
    const int wid = tid >> 5;
    const int wm0 = (wid & 1) * 64;
    const int wn0 = (wid >> 1) * 32;
    const int m0 = blockIdx.x * BM;
    const int n0 = blockIdx.y * BN;

    float acc[4][4][4];
#pragma unroll
    for (int i = 0; i < 4; i++)
#pragma unroll
        for (int j = 0; j < 4; j++)
#pragma unroll
            for (int v = 0; v < 4; v++) acc[i][j][v] = 0.0f;

    load_chunk(sb, tid, Ahi, Alo, Bhi, Blo, m0, n0, 0);
    CP_COMMIT();

#pragma unroll 1
    for (int ch = 0; ch < NCH; ch++) {
        if (ch + 1 < NCH) {
            load_chunk(sb + ((ch + 1) & 1) * BUFB, tid, Ahi, Alo, Bhi, Blo,
                       m0, n0, (ch + 1) * BK);
            CP_COMMIT();
            cp_wait<1>();
        } else {
            cp_wait<0>();
        }
        __syncthreads();

        const uint32_t sbuf = sb + (ch & 1) * BUFB;
        const uint32_t sAh = sbuf;
        const uint32_t sAl = sbuf + TSB;
        const uint32_t sBh = sbuf + 2 * TSB;
        const uint32_t sBl = sbuf + 3 * TSB;

#pragma unroll
        for (int ks = 0; ks < 2; ks++) {
            // A fragments: rows wm0 + i*16 + (lane&15), k-col = ks*16 + 8*((lane>>4)&1)
            const int arow = wm0 + (lane & 15);
            const int acolb = (ks * 16 + 8 * ((lane >> 4) & 1)) * 2;
            uint32_t ah[4][4], al[4][4];
#pragma unroll
            for (int i = 0; i < 4; i++) {
                const uint32_t off = (uint32_t)(arow + i * 16) * RSB + acolb;
                ldsm_x4(ah[i][0], ah[i][1], ah[i][2], ah[i][3], sAh + off);
                ldsm_x4(al[i][0], al[i][1], al[i][2], al[i][3], sAl + off);
            }
            // B fragments: 2 x4 loads cover 4 n8 blocks
            uint32_t bh[4][2], bl[4][2];
#pragma unroll
            for (int jj = 0; jj < 2; jj++) {
                const int nrow = wn0 + 8 * (jj * 2 + ((lane >> 4) & 1)) + (lane & 7);
                const int kcolb = (ks * 16 + 8 * ((lane >> 3) & 1)) * 2;
                const uint32_t off = (uint32_t)nrow * RSB + kcolb;
                ldsm_x4(bh[jj*2][0], bh[jj*2][1], bh[jj*2+1][0], bh[jj*2+1][1], sBh + off);
                ldsm_x4(bl[jj*2][0], bl[jj*2][1], bl[jj*2+1][0], bl[jj*2+1][1], sBl + off);
            }
#pragma unroll
            for (int i = 0; i < 4; i++)
#pragma unroll
                for (int j = 0; j < 4; j++) {
                    mma16816(acc[i][j], ah[i], bh[j]);
                    mma16816(acc[i][j], ah[i], bl[j]);
                    mma16816(acc[i][j], al[i], bh[j]);
                }
        }
        __syncthreads();
    }

    // epilogue: frag (i,j): c0,c1 at (row, col..col+1), c2,c3 at (row+8, col..col+1)
    const int frow = lane >> 2;
    const int fcol = 2 * (lane & 3);
#pragma unroll
    for (int i = 0; i < 4; i++) {
#pragma unroll
        for (int j = 0; j < 4; j++) {
            const int m = m0 + wm0 + i * 16 + frow;
            const int n = n0 + wn0 + j * 8 + fcol;
            if (PERM) {
                const int b = m >> 12, s = m & (SEQ - 1);
                const int h = n >> 6, d = n & 63;
                float* cp = C + (((size_t)(b * NH + h) * SEQ + s) * DH) + d;
                *(float2*)cp = make_float2(acc[i][j][0], acc[i][j][1]);
                float* cp2 = C + (((size_t)(b * NH + h) * SEQ + (((m + 8) & (SEQ - 1)))) * DH) + d;
                // rows m and m+8 are within the same 16-block, same batch
                *(float2*)cp2 = make_float2(acc[i][j][2], acc[i][j][3]);
            } else {
                float* cp = C + (size_t)m * HID + n;
                *(float2*)cp = make_float2(acc[i][j][0], acc[i][j][1]);
                *(float2*)(cp + 8 * HID) = make_float2(acc[i][j][2], acc[i][j][3]);
            }
        }
    }
}

__global__ __launch_bounds__(256, 1)
void qkv_mma_kernel()
{
    const int z = blockIdx.z;
    float* C = (z == 0) ? g_Q : (z == 1) ? g_K : g_V;
    gemm_body<1>(g_Xhi, g_Xlo,
                 g_Whi + (size_t)z * WELEMS, g_Wlo + (size_t)z * WELEMS, C);
}

__global__ __launch_bounds__(256, 1)
void oproj_mma_kernel(float* __restrict__ out)
{
    gemm_body<0>(g_Ahi, g_Alo, g_Whi + 3 * WELEMS, g_Wlo + 3 * WELEMS, out);
}

// ---------------------------------------------------------------------------
// Sliding-window causal attention (fp32). One thread per query, 64 q/block.
// Writes bf16 hi/lo split directly for the O-projection.
// ---------------------------------------------------------------------------
__global__ __launch_bounds__(64)
void attn_kernel(const int* __restrict__ attn_mask)
{
    const int qb = blockIdx.x;
    const int h  = blockIdx.y;
    const int b  = blockIdx.z;
    const int tid = threadIdx.x;
    const int q  = qb * 64 + tid;

    const float* __restrict__ Qh = g_Q + (size_t)(b * NH + h) * SEQ * DH;
    const float* __restrict__ Kh = g_K + (size_t)(b * NH + h) * SEQ * DH;
    const float* __restrict__ Vh = g_V + (size_t)(b * NH + h) * SEQ * DH;

    __shared__ float Ks[64 * DH];
    __shared__ float Vs[64 * DH];
    __shared__ int   msk[64];

    float qv[DH];
    {
        const float4* qp = (const float4*)(Qh + (size_t)q * DH);
#pragma unroll
        for (int i = 0; i < DH / 4; i++) {
            float4 f = qp[i];
            qv[i*4+0] = f.x; qv[i*4+1] = f.y; qv[i*4+2] = f.z; qv[i*4+3] = f.w;
        }
    }

    float mrun = -INFINITY, lrun = 0.0f;
    float o[DH];
#pragma unroll
    for (int d = 0; d < DH; d++) o[d] = 0.0f;

    const int c_lo = (qb >= 8) ? (qb - 8) : 0;

    for (int c = c_lo; c <= qb; c++) {
        const float4* Ksrc = (const float4*)(Kh + (size_t)c * 64 * DH);
        const float4* Vsrc = (const float4*)(Vh + (size_t)c * 64 * DH);
        float4* Kd = (float4*)Ks;
        float4* Vd = (float4*)Vs;
#pragma unroll
        for (int i = 0; i < 16; i++) {
            Kd[tid + i * 64] = Ksrc[tid + i * 64];
            Vd[tid + i * 64] = Vsrc[tid + i * 64];
        }
        msk[tid] = attn_mask[b * SEQ + c * 64 + tid];
        __syncthreads();

        const int jj0 = c * 64;
        for (int j = 0; j < 64; j++) {
            const int jj = jj0 + j;
            const bool valid = (jj <= q) && (jj >= q - (WIN - 1)) && (msk[j] != 0);
            if (valid) {
                const float4* kr = (const float4*)&Ks[j * DH];
                float s = 0.0f;
#pragma unroll
                for (int d4 = 0; d4 < DH / 4; d4++) {
                    float4 k4 = kr[d4];
                    s = fmaf(qv[d4*4+0], k4.x, s);
                    s = fmaf(qv[d4*4+1], k4.y, s);
                    s = fmaf(qv[d4*4+2], k4.z, s);
                    s = fmaf(qv[d4*4+3], k4.w, s);
                }
                s *= 0.125f;
                if (s > mrun) {
                    const float corr = __expf(mrun - s);
                    lrun *= corr;
#pragma unroll
                    for (int d = 0; d < DH; d++) o[d] *= corr;
                    mrun = s;
                }
                const float p = __expf(s - mrun);
                lrun += p;
                const float4* vr = (const float4*)&Vs[j * DH];
#pragma unroll
                for (int d4 = 0; d4 < DH / 4; d4++) {
                    float4 v4 = vr[d4];
                    o[d4*4+0] = fmaf(p, v4.x, o[d4*4+0]);
                    o[d4*4+1] = fmaf(p, v4.y, o[d4*4+1]);
                    o[d4*4+2] = fmaf(p, v4.z, o[d4*4+2]);
                    o[d4*4+3] = fmaf(p, v4.w, o[d4*4+3]);
                }
            }
        }
        __syncthreads();
    }

    const float inv = 1.0f / lrun;
    __nv_bfloat16* ph = g_Ahi + ((size_t)(b * SEQ) + q) * HID + h * DH;
    __nv_bfloat16* pl = g_Alo + ((size_t)(b * SEQ) + q) * HID + h * DH;
#pragma unroll
    for (int d4 = 0; d4 < DH / 4; d4++) {
        float v0 = o[d4*4+0] * inv, v1 = o[d4*4+1] * inv;
        float v2 = o[d4*4+2] * inv, v3 = o[d4*4+3] * inv;
        __nv_bfloat16 h0 = __float2bfloat16(v0), h1 = __float2bfloat16(v1);
        __nv_bfloat16 h2 = __float2bfloat16(v2), h3 = __float2bfloat16(v3);
        ushort4 uh, ul;
        uh.x = __bfloat16_as_ushort(h0); uh.y = __bfloat16_as_ushort(h1);
        uh.z = __bfloat16_as_ushort(h2); uh.w = __bfloat16_as_ushort(h3);
        ul.x = __bfloat16_as_ushort(__float2bfloat16(v0 - __bfloat162float(h0)));
        ul.y = __bfloat16_as_ushort(__float2bfloat16(v1 - __bfloat162float(h1)));
        ul.z = __bfloat16_as_ushort(__float2bfloat16(v2 - __bfloat162float(h2)));
        ul.w = __bfloat16_as_ushort(__float2bfloat16(v3 - __bfloat162float(h3)));
        *(ushort4*)(ph + d4 * 4) = uh;
        *(ushort4*)(pl + d4 * 4) = ul;
    }
}

// ---------------------------------------------------------------------------
// Launch
// ---------------------------------------------------------------------------
extern "C" void kernel_launch(void* const* d_in, const int* in_sizes, int n_in,
                              void* d_out, int out_size)
{
    const float* x    = (const float*)d_in[0];
    const int*   mask = (const int*)  d_in[1];
    const float* Wq   = (const float*)d_in[2];
    const float* Wk   = (const float*)d_in[3];
    const float* Wv   = (const float*)d_in[4];
    const float* Wo   = (const float*)d_in[5];
    float* out = (float*)d_out;

    static bool attr_set = false;
    if (!attr_set) {
        cudaFuncSetAttribute(qkv_mma_kernel,   cudaFuncAttributeMaxDynamicSharedMemorySize, GSMEM);
        cudaFuncSetAttribute(oproj_mma_kernel, cudaFuncAttributeMaxDynamicSharedMemorySize, GSMEM);
        attr_set = true;
    }

    split_kernel<<<12288, 256>>>(x, Wq, Wk, Wv, Wo);

    dim3 qgrid(MTOT / BM, HID / BN, 3);
    qkv_mma_kernel<<<qgrid, 256, GSMEM>>>();

    dim3 agrid(SEQ / 64, NH, BATCH);
    attn_kernel<<<agrid, 64>>>(mask);

    dim3 ogrid(MTOT / BM, HID / BN, 1);
    oproj_mma_kernel<<<ogrid, 256, GSMEM>>>(out);
}

// round 7
// speedup vs baseline: 1.7630x; 1.0759x over previous
#include <cuda_runtime.h>
#include <cuda_bf16.h>
#include <math.h>
#include <stdint.h>

// Problem constants
#define HID   1024
#define NH    16
#define DH    64
#define SEQ   4096
#define BATCH 2
#define WIN   512
#define MTOT  (BATCH*SEQ)          // 8192 tokens
#define XELEMS ((size_t)MTOT*HID)  // 8M
#define WELEMS ((size_t)HID*HID)   // 1M

// ---------------------------------------------------------------------------
// Scratch (__device__ globals; no allocations allowed)
// ---------------------------------------------------------------------------
__device__ __nv_bfloat16 g_Xhi[XELEMS];
__device__ __nv_bfloat16 g_Xlo[XELEMS];
__device__ __nv_bfloat16 g_Whi[4 * WELEMS];   // q,k,v,o
__device__ __nv_bfloat16 g_Wlo[4 * WELEMS];
__device__ __nv_bfloat16 g_Qhi[XELEMS];       // [b,h,s,d], pre-scaled by 1/8
__device__ __nv_bfloat16 g_Qlo[XELEMS];
__device__ __nv_bfloat16 g_Khi[XELEMS];
__device__ __nv_bfloat16 g_Klo[XELEMS];
__device__ __nv_bfloat16 g_Vhi[XELEMS];
__device__ __nv_bfloat16 g_Vlo[XELEMS];
__device__ __nv_bfloat16 g_Ahi[XELEMS];       // attn out, [token, HID] split
__device__ __nv_bfloat16 g_Alo[XELEMS];

// ---------------------------------------------------------------------------
// PTX helpers (baseline PTX only — compute_103-safe)
// ---------------------------------------------------------------------------
__device__ __forceinline__ uint32_t smem_u32(const void* p) {
    uint32_t a;
    asm("{ .reg .u64 t; cvta.to.shared.u64 t, %1; cvt.u32.u64 %0, t; }" : "=r"(a) : "l"(p));
    return a;
}
__device__ __forceinline__ void cp16(uint32_t dst, const void* src) {
    asm volatile("cp.async.cg.shared.global [%0], [%1], 16;" :: "r"(dst), "l"(src));
}
#define CP_COMMIT() asm volatile("cp.async.commit_group;" ::: "memory")
template <int N>
__device__ __forceinline__ void cp_wait() {
    asm volatile("cp.async.wait_group %0;" :: "n"(N) : "memory");
}
__device__ __forceinline__ void ldsm_x4(uint32_t& r0, uint32_t& r1, uint32_t& r2, uint32_t& r3, uint32_t a) {
    asm volatile("ldmatrix.sync.aligned.m8n8.x4.shared.b16 {%0,%1,%2,%3}, [%4];"
                 : "=r"(r0), "=r"(r1), "=r"(r2), "=r"(r3) : "r"(a));
}
__device__ __forceinline__ void ldsm_x4_t(uint32_t& r0, uint32_t& r1, uint32_t& r2, uint32_t& r3, uint32_t a) {
    asm volatile("ldmatrix.sync.aligned.m8n8.x4.trans.shared.b16 {%0,%1,%2,%3}, [%4];"
                 : "=r"(r0), "=r"(r1), "=r"(r2), "=r"(r3) : "r"(a));
}
__device__ __forceinline__ void mma16816(float* c, const uint32_t* a, const uint32_t* b) {
    asm volatile(
        "mma.sync.aligned.m16n8k16.row.col.f32.bf16.bf16.f32 "
        "{%0,%1,%2,%3}, {%4,%5,%6,%7}, {%8,%9}, {%0,%1,%2,%3};"
        : "+f"(c[0]), "+f"(c[1]), "+f"(c[2]), "+f"(c[3])
        : "r"(a[0]), "r"(a[1]), "r"(a[2]), "r"(a[3]), "r"(b[0]), "r"(b[1]));
}
// pack two floats -> bf16x2 (lo = a, hi = b)
__device__ __forceinline__ uint32_t bfpack(float a, float b) {
    uint32_t r;
    asm("cvt.rn.bf16x2.f32 %0, %1, %2;" : "=r"(r) : "f"(b), "f"(a));
    return r;
}

// ---------------------------------------------------------------------------
// fp32 -> bf16 hi/lo split of x and the 4 weight matrices
// ---------------------------------------------------------------------------
__global__ __launch_bounds__(256)
void split_kernel(const float* __restrict__ x,
                  const float* __restrict__ Wq, const float* __restrict__ Wk,
                  const float* __restrict__ Wv, const float* __restrict__ Wo)
{
    size_t t = (size_t)blockIdx.x * 256 + threadIdx.x;
    size_t e = t * 4;
    const float* src;
    __nv_bfloat16 *dh, *dl;
    if (e < XELEMS) {
        src = x + e; dh = g_Xhi + e; dl = g_Xlo + e;
    } else {
        size_t r = e - XELEMS;
        int w = (int)(r >> 20);
        size_t off = r & (WELEMS - 1);
        const float* Ws[4] = {Wq, Wk, Wv, Wo};
        src = Ws[w] + off;
        dh = g_Whi + (size_t)w * WELEMS + off;
        dl = g_Wlo + (size_t)w * WELEMS + off;
    }
    float4 v = *(const float4*)src;
    __nv_bfloat16 h0 = __float2bfloat16(v.x), h1 = __float2bfloat16(v.y);
    __nv_bfloat16 h2 = __float2bfloat16(v.z), h3 = __float2bfloat16(v.w);
    ushort4 uh, ul;
    uh.x = __bfloat16_as_ushort(h0); uh.y = __bfloat16_as_ushort(h1);
    uh.z = __bfloat16_as_ushort(h2); uh.w = __bfloat16_as_ushort(h3);
    ul.x = __bfloat16_as_ushort(__float2bfloat16(v.x - __bfloat162float(h0)));
    ul.y = __bfloat16_as_ushort(__float2bfloat16(v.y - __bfloat162float(h1)));
    ul.z = __bfloat16_as_ushort(__float2bfloat16(v.z - __bfloat162float(h2)));
    ul.w = __bfloat16_as_ushort(__float2bfloat16(v.w - __bfloat162float(h3)));
    *(ushort4*)dh = uh;
    *(ushort4*)dl = ul;
}

// ---------------------------------------------------------------------------
// bf16-split GEMM via mma.sync: C[m,n] = sum_k A[m,k]*W[n,k]
// MODE 0: fp32 output to C.  MODE 1: bf16 hi/lo output to [b,h,s,d] (scaled).
// ---------------------------------------------------------------------------
#define BM 128
#define BN 128
#define BK 32
#define RSB 80
#define TSB (128 * RSB)
#define BUFB (4 * TSB)
#define GSMEM (2 * BUFB)
#define NCH (HID / BK)

__device__ __forceinline__ void load_chunk(
    uint32_t sbuf, int tid,
    const __nv_bfloat16* __restrict__ Ahi, const __nv_bfloat16* __restrict__ Alo,
    const __nv_bfloat16* __restrict__ Bhi, const __nv_bfloat16* __restrict__ Blo,
    int m0, int n0, int k0)
{
#pragma unroll
    for (int i = 0; i < 8; i++) {
        const int tile = i >> 1;
        const int idx = tid + (i & 1) * 256;
        const int r = idx >> 2;
        const int c = idx & 3;
        const __nv_bfloat16* base =
            (tile == 0) ? Ahi : (tile == 1) ? Alo : (tile == 2) ? Bhi : Blo;
        const int row0 = (tile < 2) ? m0 : n0;
        const __nv_bfloat16* src = base + (size_t)(row0 + r) * HID + k0 + c * 8;
        cp16(sbuf + tile * TSB + r * RSB + c * 16, src);
    }
}

template <int MODE>
__device__ __forceinline__ void gemm_body(
    const __nv_bfloat16* __restrict__ Ahi, const __nv_bfloat16* __restrict__ Alo,
    const __nv_bfloat16* __restrict__ Bhi, const __nv_bfloat16* __restrict__ Blo,
    float* __restrict__ C, __nv_bfloat16* __restrict__ Chi,
    __nv_bfloat16* __restrict__ Clo, float scale)
{
    extern __shared__ char smem[];
    const uint32_t sb = smem_u32(smem);
    const int tid = threadIdx.x;
    const int lane = tid & 31;
    const int wid = tid >> 5;
    const int wm0 = (wid & 1) * 64;
    const int wn0 = (wid >> 1) * 32;
    const int m0 = blockIdx.x * BM;
    const int n0 = blockIdx.y * BN;

    float acc[4][4][4];
#pragma unroll
    for (int i = 0; i < 4; i++)
#pragma unroll
        for (int j = 0; j < 4; j++)
#pragma unroll
            for (int v = 0; v < 4; v++) acc[i][j][v] = 0.0f;

    load_chunk(sb, tid, Ahi, Alo, Bhi, Blo, m0, n0, 0);
    CP_COMMIT();

#pragma unroll 1
    for (int ch = 0; ch < NCH; ch++) {
        if (ch + 1 < NCH) {
            load_chunk(sb + ((ch + 1) & 1) * BUFB, tid, Ahi, Alo, Bhi, Blo,
                       m0, n0, (ch + 1) * BK);
            CP_COMMIT();
            cp_wait<1>();
        } else {
            cp_wait<0>();
        }
        __syncthreads();

        const uint32_t sbuf = sb + (ch & 1) * BUFB;
        const uint32_t sAh = sbuf;
        const uint32_t sAl = sbuf + TSB;
        const uint32_t sBh = sbuf + 2 * TSB;
        const uint32_t sBl = sbuf + 3 * TSB;

#pragma unroll
        for (int ks = 0; ks < 2; ks++) {
            const int arow = wm0 + (lane & 15);
            const int acolb = (ks * 16 + 8 * ((lane >> 4) & 1)) * 2;
            uint32_t ah[4][4], al[4][4];
#pragma unroll
            for (int i = 0; i < 4; i++) {
                const uint32_t off = (uint32_t)(arow + i * 16) * RSB + acolb;
                ldsm_x4(ah[i][0], ah[i][1], ah[i][2], ah[i][3], sAh + off);
                ldsm_x4(al[i][0], al[i][1], al[i][2], al[i][3], sAl + off);
            }
            uint32_t bh[4][2], bl[4][2];
#pragma unroll
            for (int jj = 0; jj < 2; jj++) {
                const int nrow = wn0 + 8 * (jj * 2 + ((lane >> 4) & 1)) + (lane & 7);
                const int kcolb = (ks * 16 + 8 * ((lane >> 3) & 1)) * 2;
                const uint32_t off = (uint32_t)nrow * RSB + kcolb;
                ldsm_x4(bh[jj*2][0], bh[jj*2][1], bh[jj*2+1][0], bh[jj*2+1][1], sBh + off);
                ldsm_x4(bl[jj*2][0], bl[jj*2][1], bl[jj*2+1][0], bl[jj*2+1][1], sBl + off);
            }
#pragma unroll
            for (int i = 0; i < 4; i++)
#pragma unroll
                for (int j = 0; j < 4; j++) {
                    mma16816(acc[i][j], ah[i], bh[j]);
                    mma16816(acc[i][j], ah[i], bl[j]);
                    mma16816(acc[i][j], al[i], bh[j]);
                }
        }
        __syncthreads();
    }

    const int frow = lane >> 2;
    const int fcol = 2 * (lane & 3);
#pragma unroll
    for (int i = 0; i < 4; i++) {
#pragma unroll
        for (int j = 0; j < 4; j++) {
            const int m = m0 + wm0 + i * 16 + frow;
            const int n = n0 + wn0 + j * 8 + fcol;
            if (MODE == 1) {
                const int b = m >> 12, s = m & (SEQ - 1);
                const int h = n >> 6, d = n & 63;
                const size_t base0 = (((size_t)(b * NH + h) * SEQ + s) * DH) + d;
                const size_t base1 = base0 + 8 * DH;   // row m+8, same b
                float c0 = acc[i][j][0] * scale, c1 = acc[i][j][1] * scale;
                float c2 = acc[i][j][2] * scale, c3 = acc[i][j][3] * scale;
                __nv_bfloat16 h0 = __float2bfloat16(c0), h1 = __float2bfloat16(c1);
                __nv_bfloat16 h2 = __float2bfloat16(c2), h3 = __float2bfloat16(c3);
                ushort2 u0, u1, v0, v1;
                u0.x = __bfloat16_as_ushort(h0); u0.y = __bfloat16_as_ushort(h1);
                u1.x = __bfloat16_as_ushort(h2); u1.y = __bfloat16_as_ushort(h3);
                v0.x = __bfloat16_as_ushort(__float2bfloat16(c0 - __bfloat162float(h0)));
                v0.y = __bfloat16_as_ushort(__float2bfloat16(c1 - __bfloat162float(h1)));
                v1.x = __bfloat16_as_ushort(__float2bfloat16(c2 - __bfloat162float(h2)));
                v1.y = __bfloat16_as_ushort(__float2bfloat16(c3 - __bfloat162float(h3)));
                *(ushort2*)(Chi + base0) = u0;
                *(ushort2*)(Chi + base1) = u1;
                *(ushort2*)(Clo + base0) = v0;
                *(ushort2*)(Clo + base1) = v1;
            } else {
                float* cp = C + (size_t)m * HID + n;
                *(float2*)cp = make_float2(acc[i][j][0], acc[i][j][1]);
                *(float2*)(cp + 8 * HID) = make_float2(acc[i][j][2], acc[i][j][3]);
            }
        }
    }
}

__global__ __launch_bounds__(256, 1)
void qkv_mma_kernel()
{
    const int z = blockIdx.z;
    __nv_bfloat16* Chi = (z == 0) ? g_Qhi : (z == 1) ? g_Khi : g_Vhi;
    __nv_bfloat16* Clo = (z == 0) ? g_Qlo : (z == 1) ? g_Klo : g_Vlo;
    const float scale = (z == 0) ? 0.125f : 1.0f;
    gemm_body<1>(g_Xhi, g_Xlo,
                 g_Whi + (size_t)z * WELEMS, g_Wlo + (size_t)z * WELEMS,
                 nullptr, Chi, Clo, scale);
}

__global__ __launch_bounds__(256, 1)
void oproj_mma_kernel(float* __restrict__ out)
{
    gemm_body<0>(g_Ahi, g_Alo, g_Whi + 3 * WELEMS, g_Wlo + 3 * WELEMS,
                 out, nullptr, nullptr, 1.0f);
}

// ---------------------------------------------------------------------------
// Flash attention via mma.sync. CTA = 128 queries x 1 head. 8 warps x 16 rows.
// KV chunks of 64 keys, double-buffered cp.async. bf16 splits throughout.
// ---------------------------------------------------------------------------
#define QT 128
#define TRB 144                       // smem tile row bytes (128 data + 16 pad)
#define TILEB (64 * TRB)              // 9216
#define STAGEB (4 * TILEB)            // 36864 (Khi,Klo,Vhi,Vlo)
#define ASMEM (2 * STAGEB + 512)

__device__ __forceinline__ void load_kv(
    uint32_t sb, int tid, int st, int c, size_t headoff,
    const int* __restrict__ attn_mask, int b)
{
#pragma unroll
    for (int i = 0; i < 8; i++) {
        const int idx = tid + i * 256;       // 0..2047
        const int t = idx >> 9;              // tile 0..3
        const int r = (idx >> 3) & 63;
        const int cc = idx & 7;
        const __nv_bfloat16* base =
            (t == 0) ? g_Khi : (t == 1) ? g_Klo : (t == 2) ? g_Vhi : g_Vlo;
        const __nv_bfloat16* src = base + headoff + (size_t)(c * 64 + r) * DH + cc * 8;
        cp16(sb + st * STAGEB + t * TILEB + r * TRB + cc * 16, src);
    }
    if (tid < 16)
        cp16(sb + 2 * STAGEB + st * 256 + tid * 16, attn_mask + b * SEQ + c * 64 + tid * 4);
    CP_COMMIT();
}

__global__ __launch_bounds__(256, 1)
void attn_mma_kernel(const int* __restrict__ attn_mask)
{
    extern __shared__ char smem[];
    const uint32_t sb = smem_u32(smem);
    const int tid = threadIdx.x;
    const int lane = tid & 31;
    const int wid = tid >> 5;
    const int qb = blockIdx.x;
    const int h = blockIdx.y;
    const int b = blockIdx.z;
    const int q0 = qb * QT;
    const size_t headoff = (size_t)(b * NH + h) * SEQ * DH;

    // ---- stage Q tile (hi/lo) into stage-0 buffer, read frags, then reuse ----
#pragma unroll
    for (int i = 0; i < 8; i++) {
        const int idx = tid + i * 256;       // 0..2047
        const int t = idx >> 10;             // 0 hi, 1 lo
        const int r = (idx >> 3) & 127;
        const int cc = idx & 7;
        const __nv_bfloat16* base = t ? g_Qlo : g_Qhi;
        cp16(sb + t * 18432 + r * TRB + cc * 16,
             base + headoff + (size_t)(q0 + r) * DH + cc * 8);
    }
    CP_COMMIT();
    cp_wait<0>();
    __syncthreads();

    uint32_t qh[4][4], ql[4][4];
    {
        const int arow = wid * 16 + (lane & 15);
#pragma unroll
        for (int ks = 0; ks < 4; ks++) {
            const uint32_t off = (uint32_t)arow * TRB + (ks * 16 + 8 * ((lane >> 4) & 1)) * 2;
            ldsm_x4(qh[ks][0], qh[ks][1], qh[ks][2], qh[ks][3], sb + off);
            ldsm_x4(ql[ks][0], ql[ks][1], ql[ks][2], ql[ks][3], sb + 18432 + off);
        }
    }
    __syncthreads();   // done with Q staging area

    const int r0g = q0 + wid * 16 + (lane >> 2);
    const int r1g = r0g + 8;

    float m0r = -1e4f, m1r = -1e4f, l0 = 0.0f, l1 = 0.0f;
    float o[8][4];
#pragma unroll
    for (int j = 0; j < 8; j++)
#pragma unroll
        for (int v = 0; v < 4; v++) o[j][v] = 0.0f;

    const int clo = (2 * qb >= 8) ? (2 * qb - 8) : 0;
    const int chi = 2 * qb + 1;

    load_kv(sb, tid, 0, clo, headoff, attn_mask, b);

#pragma unroll 1
    for (int c = clo; c <= chi; c++) {
        const int st = (c - clo) & 1;
        if (c < chi) {
            load_kv(sb, tid, st ^ 1, c + 1, headoff, attn_mask, b);
            cp_wait<1>();
        } else {
            cp_wait<0>();
        }
        __syncthreads();

        const uint32_t kb = sb + st * STAGEB;

        // ---- S = Q K^T (3 split terms) ----
        float p[8][4];
#pragma unroll
        for (int j = 0; j < 8; j++)
#pragma unroll
            for (int v = 0; v < 4; v++) p[j][v] = 0.0f;

#pragma unroll
        for (int ks = 0; ks < 4; ks++) {
            uint32_t bh[8][2], bl[8][2];
#pragma unroll
            for (int jj = 0; jj < 4; jj++) {
                const int nrow = 16 * jj + 8 * ((lane >> 4) & 1) + (lane & 7);
                const int kcolb = (ks * 16 + 8 * ((lane >> 3) & 1)) * 2;
                const uint32_t off = (uint32_t)nrow * TRB + kcolb;
                ldsm_x4(bh[jj*2][0], bh[jj*2][1], bh[jj*2+1][0], bh[jj*2+1][1], kb + off);
                ldsm_x4(bl[jj*2][0], bl[jj*2][1], bl[jj*2+1][0], bl[jj*2+1][1], kb + TILEB + off);
            }
#pragma unroll
            for (int j = 0; j < 8; j++) {
                mma16816(p[j], qh[ks], bh[j]);
                mma16816(p[j], qh[ks], bl[j]);
                mma16816(p[j], ql[ks], bh[j]);
            }
        }

        // ---- mask + online softmax ----
        const int* mk = (const int*)(smem + 2 * STAGEB + st * 256);
        const int c64 = c * 64;
#pragma unroll
        for (int j = 0; j < 8; j++) {
            const int kloc = j * 8 + 2 * (lane & 3);
            const int kg = c64 + kloc;
            const int mv0 = mk[kloc], mv1 = mk[kloc + 1];
            if (!(kg     <= r0g && kg     >= r0g - (WIN-1) && mv0)) p[j][0] = -1e30f;
            if (!(kg + 1 <= r0g && kg + 1 >= r0g - (WIN-1) && mv1)) p[j][1] = -1e30f;
            if (!(kg     <= r1g && kg     >= r1g - (WIN-1) && mv0)) p[j][2] = -1e30f;
            if (!(kg + 1 <= r1g && kg + 1 >= r1g - (WIN-1) && mv1)) p[j][3] = -1e30f;
        }
        float mx0 = -1e30f, mx1 = -1e30f;
#pragma unroll
        for (int j = 0; j < 8; j++) {
            mx0 = fmaxf(mx0, fmaxf(p[j][0], p[j][1]));
            mx1 = fmaxf(mx1, fmaxf(p[j][2], p[j][3]));
        }
        mx0 = fmaxf(mx0, __shfl_xor_sync(0xffffffffu, mx0, 1));
        mx0 = fmaxf(mx0, __shfl_xor_sync(0xffffffffu, mx0, 2));
        mx1 = fmaxf(mx1, __shfl_xor_sync(0xffffffffu, mx1, 1));
        mx1 = fmaxf(mx1, __shfl_xor_sync(0xffffffffu, mx1, 2));

        const float mn0 = fmaxf(m0r, mx0);
        const float mn1 = fmaxf(m1r, mx1);
        const float cr0 = __expf(m0r - mn0);
        const float cr1 = __expf(m1r - mn1);
        m0r = mn0; m1r = mn1;
        l0 *= cr0; l1 *= cr1;
#pragma unroll
        for (int j = 0; j < 8; j++) {
            o[j][0] *= cr0; o[j][1] *= cr0;
            o[j][2] *= cr1; o[j][3] *= cr1;
        }
        float s0 = 0.0f, s1 = 0.0f;
#pragma unroll
        for (int j = 0; j < 8; j++) {
            p[j][0] = __expf(p[j][0] - mn0); s0 += p[j][0];
            p[j][1] = __expf(p[j][1] - mn0); s0 += p[j][1];
            p[j][2] = __expf(p[j][2] - mn1); s1 += p[j][2];
            p[j][3] = __expf(p[j][3] - mn1); s1 += p[j][3];
        }
        // FIX (round 6 bug): the mma-produced O sums over ALL keys in the
        // lane-quad, so l must too — quad-reduce the partial sums.
        s0 += __shfl_xor_sync(0xffffffffu, s0, 1);
        s0 += __shfl_xor_sync(0xffffffffu, s0, 2);
        s1 += __shfl_xor_sync(0xffffffffu, s1, 1);
        s1 += __shfl_xor_sync(0xffffffffu, s1, 2);
        l0 += s0; l1 += s1;

        // ---- O += P V (3 split terms) ----
#pragma unroll
        for (int ks2 = 0; ks2 < 4; ks2++) {
            uint32_t ahp[4], alp[4];
            {
                const float p00 = p[2*ks2][0],   p01 = p[2*ks2][1];
                const float p02 = p[2*ks2][2],   p03 = p[2*ks2][3];
                const float p10 = p[2*ks2+1][0], p11 = p[2*ks2+1][1];
                const float p12 = p[2*ks2+1][2], p13 = p[2*ks2+1][3];
                ahp[0] = bfpack(p00, p01);
                ahp[1] = bfpack(p02, p03);
                ahp[2] = bfpack(p10, p11);
                ahp[3] = bfpack(p12, p13);
                const __nv_bfloat162* hp0 = (const __nv_bfloat162*)&ahp[0];
                const __nv_bfloat162* hp1 = (const __nv_bfloat162*)&ahp[1];
                const __nv_bfloat162* hp2 = (const __nv_bfloat162*)&ahp[2];
                const __nv_bfloat162* hp3 = (const __nv_bfloat162*)&ahp[3];
                alp[0] = bfpack(p00 - __bfloat162float(hp0->x), p01 - __bfloat162float(hp0->y));
                alp[1] = bfpack(p02 - __bfloat162float(hp1->x), p03 - __bfloat162float(hp1->y));
                alp[2] = bfpack(p10 - __bfloat162float(hp2->x), p11 - __bfloat162float(hp2->y));
                alp[3] = bfpack(p12 - __bfloat162float(hp3->x), p13 - __bfloat162float(hp3->y));
            }
            uint32_t bvh[8][2], bvl[8][2];
#pragma unroll
            for (int jj = 0; jj < 4; jj++) {
                const int vrow = 16 * ks2 + (lane & 7) + 8 * ((lane >> 3) & 1);
                const int colb = (2 * jj + (lane >> 4)) * 16;
                const uint32_t off = (uint32_t)vrow * TRB + colb;
                ldsm_x4_t(bvh[jj*2][0], bvh[jj*2][1], bvh[jj*2+1][0], bvh[jj*2+1][1],
                          kb + 2 * TILEB + off);
                ldsm_x4_t(bvl[jj*2][0], bvl[jj*2][1], bvl[jj*2+1][0], bvl[jj*2+1][1],
                          kb + 3 * TILEB + off);
            }
#pragma unroll
            for (int j = 0; j < 8; j++) {
                mma16816(o[j], ahp, bvh[j]);
                mma16816(o[j], ahp, bvl[j]);
                mma16816(o[j], alp, bvh[j]);
            }
        }
        __syncthreads();
    }

    // ---- normalize + write bf16 hi/lo to [token, HID] ----
    const float i0 = 1.0f / fmaxf(l0, 1e-30f);
    const float i1 = 1.0f / fmaxf(l1, 1e-30f);
    const size_t t0 = (size_t)(b * SEQ + r0g) * HID + h * DH;
    const size_t t1 = (size_t)(b * SEQ + r1g) * HID + h * DH;
#pragma unroll
    for (int j = 0; j < 8; j++) {
        const int d = j * 8 + 2 * (lane & 3);
        float a0 = o[j][0] * i0, a1 = o[j][1] * i0;
        float a2 = o[j][2] * i1, a3 = o[j][3] * i1;
        __nv_bfloat16 h0 = __float2bfloat16(a0), h1 = __float2bfloat16(a1);
        __nv_bfloat16 h2 = __float2bfloat16(a2), h3 = __float2bfloat16(a3);
        ushort2 u0, u1, v0, v1;
        u0.x = __bfloat16_as_ushort(h0); u0.y = __bfloat16_as_ushort(h1);
        u1.x = __bfloat16_as_ushort(h2); u1.y = __bfloat16_as_ushort(h3);
        v0.x = __bfloat16_as_ushort(__float2bfloat16(a0 - __bfloat162float(h0)));
        v0.y = __bfloat16_as_ushort(__float2bfloat16(a1 - __bfloat162float(h1)));
        v1.x = __bfloat16_as_ushort(__float2bfloat16(a2 - __bfloat162float(h2)));
        v1.y = __bfloat16_as_ushort(__float2bfloat16(a3 - __bfloat162float(h3)));
        *(ushort2*)(g_Ahi + t0 + d) = u0;
        *(ushort2*)(g_Ahi + t1 + d) = u1;
        *(ushort2*)(g_Alo + t0 + d) = v0;
        *(ushort2*)(g_Alo + t1 + d) = v1;
    }
}

// ---------------------------------------------------------------------------
// Launch
// ---------------------------------------------------------------------------
extern "C" void kernel_launch(void* const* d_in, const int* in_sizes, int n_in,
                              void* d_out, int out_size)
{
    const float* x    = (const float*)d_in[0];
    const int*   mask = (const int*)  d_in[1];
    const float* Wq   = (const float*)d_in[2];
    const float* Wk   = (const float*)d_in[3];
    const float* Wv   = (const float*)d_in[4];
    const float* Wo   = (const float*)d_in[5];
    float* out = (float*)d_out;

    static bool attr_set = false;
    if (!attr_set) {
        cudaFuncSetAttribute(qkv_mma_kernel,   cudaFuncAttributeMaxDynamicSharedMemorySize, GSMEM);
        cudaFuncSetAttribute(oproj_mma_kernel, cudaFuncAttributeMaxDynamicSharedMemorySize, GSMEM);
        cudaFuncSetAttribute(attn_mma_kernel,  cudaFuncAttributeMaxDynamicSharedMemorySize, ASMEM);
        attr_set = true;
    }

    split_kernel<<<12288, 256>>>(x, Wq, Wk, Wv, Wo);

    dim3 qgrid(MTOT / BM, HID / BN, 3);
    qkv_mma_kernel<<<qgrid, 256, GSMEM>>>();

    dim3 agrid(SEQ / QT, NH, BATCH);
    attn_mma_kernel<<<agrid, 256, ASMEM>>>(mask);

    dim3 ogrid(MTOT / BM, HID / BN, 1);
    oproj_mma_kernel<<<ogrid, 256, GSMEM>>>(out);
}

// round 8
// speedup vs baseline: 3.0268x; 1.7168x over previous
#include <cuda_runtime.h>
#include <cuda_bf16.h>
#include <math.h>
#include <stdint.h>

// Problem constants
#define HID   1024
#define NH    16
#define DH    64
#define SEQ   4096
#define BATCH 2
#define WIN   512
#define MTOT  (BATCH*SEQ)          // 8192 tokens
#define XELEMS ((size_t)MTOT*HID)  // 8M
#define WELEMS ((size_t)HID*HID)   // 1M

// ---------------------------------------------------------------------------
// Scratch (__device__ globals; no allocations allowed)
// ---------------------------------------------------------------------------
__device__ __nv_bfloat16 g_Xhi[XELEMS];
__device__ __nv_bfloat16 g_Xlo[XELEMS];
__device__ __nv_bfloat16 g_Whi[4 * WELEMS];   // q,k,v,o
__device__ __nv_bfloat16 g_Wlo[4 * WELEMS];
__device__ __nv_bfloat16 g_Qhi[XELEMS];       // [b,h,s,d], pre-scaled by 1/8
__device__ __nv_bfloat16 g_Qlo[XELEMS];
__device__ __nv_bfloat16 g_Khi[XELEMS];
__device__ __nv_bfloat16 g_Klo[XELEMS];
__device__ __nv_bfloat16 g_Vhi[XELEMS];
__device__ __nv_bfloat16 g_Vlo[XELEMS];
__device__ __nv_bfloat16 g_Ahi[XELEMS];       // attn out, [token, HID] split
__device__ __nv_bfloat16 g_Alo[XELEMS];

// ---------------------------------------------------------------------------
// PTX helpers (baseline PTX only — compute_103-safe)
// ---------------------------------------------------------------------------
__device__ __forceinline__ uint32_t smem_u32(const void* p) {
    uint32_t a;
    asm("{ .reg .u64 t; cvta.to.shared.u64 t, %1; cvt.u32.u64 %0, t; }" : "=r"(a) : "l"(p));
    return a;
}
__device__ __forceinline__ void cp16(uint32_t dst, const void* src) {
    asm volatile("cp.async.cg.shared.global [%0], [%1], 16;" :: "r"(dst), "l"(src));
}
#define CP_COMMIT() asm volatile("cp.async.commit_group;" ::: "memory")
template <int N>
__device__ __forceinline__ void cp_wait() {
    asm volatile("cp.async.wait_group %0;" :: "n"(N) : "memory");
}
__device__ __forceinline__ void ldsm_x4(uint32_t& r0, uint32_t& r1, uint32_t& r2, uint32_t& r3, uint32_t a) {
    asm volatile("ldmatrix.sync.aligned.m8n8.x4.shared.b16 {%0,%1,%2,%3}, [%4];"
                 : "=r"(r0), "=r"(r1), "=r"(r2), "=r"(r3) : "r"(a));
}
__device__ __forceinline__ void ldsm_x4_t(uint32_t& r0, uint32_t& r1, uint32_t& r2, uint32_t& r3, uint32_t a) {
    asm volatile("ldmatrix.sync.aligned.m8n8.x4.trans.shared.b16 {%0,%1,%2,%3}, [%4];"
                 : "=r"(r0), "=r"(r1), "=r"(r2), "=r"(r3) : "r"(a));
}
__device__ __forceinline__ void mma16816(float* c, const uint32_t* a, const uint32_t* b) {
    asm volatile(
        "mma.sync.aligned.m16n8k16.row.col.f32.bf16.bf16.f32 "
        "{%0,%1,%2,%3}, {%4,%5,%6,%7}, {%8,%9}, {%0,%1,%2,%3};"
        : "+f"(c[0]), "+f"(c[1]), "+f"(c[2]), "+f"(c[3])
        : "r"(a[0]), "r"(a[1]), "r"(a[2]), "r"(a[3]), "r"(b[0]), "r"(b[1]));
}
// pack two floats -> bf16x2 (lo = a, hi = b)
__device__ __forceinline__ uint32_t bfpack(float a, float b) {
    uint32_t r;
    asm("cvt.rn.bf16x2.f32 %0, %1, %2;" : "=r"(r) : "f"(b), "f"(a));
    return r;
}

// ---------------------------------------------------------------------------
// fp32 -> bf16 hi/lo split of x and the 4 weight matrices
// ---------------------------------------------------------------------------
__global__ __launch_bounds__(256)
void split_kernel(const float* __restrict__ x,
                  const float* __restrict__ Wq, const float* __restrict__ Wk,
                  const float* __restrict__ Wv, const float* __restrict__ Wo)
{
    size_t t = (size_t)blockIdx.x * 256 + threadIdx.x;
    size_t e = t * 4;
    const float* src;
    __nv_bfloat16 *dh, *dl;
    if (e < XELEMS) {
        src = x + e; dh = g_Xhi + e; dl = g_Xlo + e;
    } else {
        size_t r = e - XELEMS;
        int w = (int)(r >> 20);
        size_t off = r & (WELEMS - 1);
        const float* Ws[4] = {Wq, Wk, Wv, Wo};
        src = Ws[w] + off;
        dh = g_Whi + (size_t)w * WELEMS + off;
        dl = g_Wlo + (size_t)w * WELEMS + off;
    }
    float4 v = *(const float4*)src;
    __nv_bfloat16 h0 = __float2bfloat16(v.x), h1 = __float2bfloat16(v.y);
    __nv_bfloat16 h2 = __float2bfloat16(v.z), h3 = __float2bfloat16(v.w);
    ushort4 uh, ul;
    uh.x = __bfloat16_as_ushort(h0); uh.y = __bfloat16_as_ushort(h1);
    uh.z = __bfloat16_as_ushort(h2); uh.w = __bfloat16_as_ushort(h3);
    ul.x = __bfloat16_as_ushort(__float2bfloat16(v.x - __bfloat162float(h0)));
    ul.y = __bfloat16_as_ushort(__float2bfloat16(v.y - __bfloat162float(h1)));
    ul.z = __bfloat16_as_ushort(__float2bfloat16(v.z - __bfloat162float(h2)));
    ul.w = __bfloat16_as_ushort(__float2bfloat16(v.w - __bfloat162float(h3)));
    *(ushort4*)dh = uh;
    *(ushort4*)dl = ul;
}

// ---------------------------------------------------------------------------
// bf16-split GEMM via mma.sync: C[m,n] = sum_k A[m,k]*W[n,k]
// MODE 0: fp32 output to C.  MODE 1: bf16 hi/lo output to [b,h,s,d] (scaled).
// ---------------------------------------------------------------------------
#define BM 128
#define BN 128
#define BK 32
#define RSB 80
#define TSB (128 * RSB)
#define BUFB (4 * TSB)
#define GSMEM (2 * BUFB)
#define NCH (HID / BK)

__device__ __forceinline__ void load_chunk(
    uint32_t sbuf, int tid,
    const __nv_bfloat16* __restrict__ Ahi, const __nv_bfloat16* __restrict__ Alo,
    const __nv_bfloat16* __restrict__ Bhi, const __nv_bfloat16* __restrict__ Blo,
    int m0, int n0, int k0)
{
#pragma unroll
    for (int i = 0; i < 8; i++) {
        const int tile = i >> 1;
        const int idx = tid + (i & 1) * 256;
        const int r = idx >> 2;
        const int c = idx & 3;
        const __nv_bfloat16* base =
            (tile == 0) ? Ahi : (tile == 1) ? Alo : (tile == 2) ? Bhi : Blo;
        const int row0 = (tile < 2) ? m0 : n0;
        const __nv_bfloat16* src = base + (size_t)(row0 + r) * HID + k0 + c * 8;
        cp16(sbuf + tile * TSB + r * RSB + c * 16, src);
    }
}

template <int MODE>
__device__ __forceinline__ void gemm_body(
    const __nv_bfloat16* __restrict__ Ahi, const __nv_bfloat16* __restrict__ Alo,
    const __nv_bfloat16* __restrict__ Bhi, const __nv_bfloat16* __restrict__ Blo,
    float* __restrict__ C, __nv_bfloat16* __restrict__ Chi,
    __nv_bfloat16* __restrict__ Clo, float scale)
{
    extern __shared__ char smem[];
    const uint32_t sb = smem_u32(smem);
    const int tid = threadIdx.x;
    const int lane = tid & 31;
    const int wid = tid >> 5;
    const int wm0 = (wid & 1) * 64;
    const int wn0 = (wid >> 1) * 32;
    const int m0 = blockIdx.x * BM;
    const int n0 = blockIdx.y * BN;

    float acc[4][4][4];
#pragma unroll
    for (int i = 0; i < 4; i++)
#pragma unroll
        for (int j = 0; j < 4; j++)
#pragma unroll
            for (int v = 0; v < 4; v++) acc[i][j][v] = 0.0f;

    load_chunk(sb, tid, Ahi, Alo, Bhi, Blo, m0, n0, 0);
    CP_COMMIT();

#pragma unroll 1
    for (int ch = 0; ch < NCH; ch++) {
        if (ch + 1 < NCH) {
            load_chunk(sb + ((ch + 1) & 1) * BUFB, tid, Ahi, Alo, Bhi, Blo,
                       m0, n0, (ch + 1) * BK);
            CP_COMMIT();
            cp_wait<1>();
        } else {
            cp_wait<0>();
        }
        __syncthreads();

        const uint32_t sbuf = sb + (ch & 1) * BUFB;
        const uint32_t sAh = sbuf;
        const uint32_t sAl = sbuf + TSB;
        const uint32_t sBh = sbuf + 2 * TSB;
        const uint32_t sBl = sbuf + 3 * TSB;

#pragma unroll
        for (int ks = 0; ks < 2; ks++) {
            const int arow = wm0 + (lane & 15);
            const int acolb = (ks * 16 + 8 * ((lane >> 4) & 1)) * 2;
            uint32_t ah[4][4], al[4][4];
#pragma unroll
            for (int i = 0; i < 4; i++) {
                const uint32_t off = (uint32_t)(arow + i * 16) * RSB + acolb;
                ldsm_x4(ah[i][0], ah[i][1], ah[i][2], ah[i][3], sAh + off);
                ldsm_x4(al[i][0], al[i][1], al[i][2], al[i][3], sAl + off);
            }
            uint32_t bh[4][2], bl[4][2];
#pragma unroll
            for (int jj = 0; jj < 2; jj++) {
                const int nrow = wn0 + 8 * (jj * 2 + ((lane >> 4) & 1)) + (lane & 7);
                const int kcolb = (ks * 16 + 8 * ((lane >> 3) & 1)) * 2;
                const uint32_t off = (uint32_t)nrow * RSB + kcolb;
                ldsm_x4(bh[jj*2][0], bh[jj*2][1], bh[jj*2+1][0], bh[jj*2+1][1], sBh + off);
                ldsm_x4(bl[jj*2][0], bl[jj*2][1], bl[jj*2+1][0], bl[jj*2+1][1], sBl + off);
            }
#pragma unroll
            for (int i = 0; i < 4; i++)
#pragma unroll
                for (int j = 0; j < 4; j++) {
                    mma16816(acc[i][j], ah[i], bh[j]);
                    mma16816(acc[i][j], ah[i], bl[j]);
                    mma16816(acc[i][j], al[i], bh[j]);
                }
        }
        __syncthreads();
    }

    const int frow = lane >> 2;
    const int fcol = 2 * (lane & 3);
#pragma unroll
    for (int i = 0; i < 4; i++) {
#pragma unroll
        for (int j = 0; j < 4; j++) {
            const int m = m0 + wm0 + i * 16 + frow;
            const int n = n0 + wn0 + j * 8 + fcol;
            if (MODE == 1) {
                const int b = m >> 12, s = m & (SEQ - 1);
                const int h = n >> 6, d = n & 63;
                const size_t base0 = (((size_t)(b * NH + h) * SEQ + s) * DH) + d;
                const size_t base1 = base0 + 8 * DH;   // row m+8, same b
                float c0 = acc[i][j][0] * scale, c1 = acc[i][j][1] * scale;
                float c2 = acc[i][j][2] * scale, c3 = acc[i][j][3] * scale;
                __nv_bfloat16 h0 = __float2bfloat16(c0), h1 = __float2bfloat16(c1);
                __nv_bfloat16 h2 = __float2bfloat16(c2), h3 = __float2bfloat16(c3);
                ushort2 u0, u1, v0, v1;
                u0.x = __bfloat16_as_ushort(h0); u0.y = __bfloat16_as_ushort(h1);
                u1.x = __bfloat16_as_ushort(h2); u1.y = __bfloat16_as_ushort(h3);
                v0.x = __bfloat16_as_ushort(__float2bfloat16(c0 - __bfloat162float(h0)));
                v0.y = __bfloat16_as_ushort(__float2bfloat16(c1 - __bfloat162float(h1)));
                v1.x = __bfloat16_as_ushort(__float2bfloat16(c2 - __bfloat162float(h2)));
                v1.y = __bfloat16_as_ushort(__float2bfloat16(c3 - __bfloat162float(h3)));
                *(ushort2*)(Chi + base0) = u0;
                *(ushort2*)(Chi + base1) = u1;
                *(ushort2*)(Clo + base0) = v0;
                *(ushort2*)(Clo + base1) = v1;
            } else {
                float* cp = C + (size_t)m * HID + n;
                *(float2*)cp = make_float2(acc[i][j][0], acc[i][j][1]);
                *(float2*)(cp + 8 * HID) = make_float2(acc[i][j][2], acc[i][j][3]);
            }
        }
    }
}

__global__ __launch_bounds__(256, 2)
void qkv_mma_kernel()
{
    const int z = blockIdx.z;
    __nv_bfloat16* Chi = (z == 0) ? g_Qhi : (z == 1) ? g_Khi : g_Vhi;
    __nv_bfloat16* Clo = (z == 0) ? g_Qlo : (z == 1) ? g_Klo : g_Vlo;
    const float scale = (z == 0) ? 0.125f : 1.0f;
    gemm_body<1>(g_Xhi, g_Xlo,
                 g_Whi + (size_t)z * WELEMS, g_Wlo + (size_t)z * WELEMS,
                 nullptr, Chi, Clo, scale);
}

__global__ __launch_bounds__(256, 2)
void oproj_mma_kernel(float* __restrict__ out)
{
    gemm_body<0>(g_Ahi, g_Alo, g_Whi + 3 * WELEMS, g_Wlo + 3 * WELEMS,
                 out, nullptr, nullptr, 1.0f);
}

// ---------------------------------------------------------------------------
// Flash attention via mma.sync. CTA = 128 queries x 1 head. 8 warps x 16 rows.
// KV chunks of 64 keys, double-buffered cp.async. bf16 splits throughout.
// ---------------------------------------------------------------------------
#define QT 128
#define TRB 144                       // smem tile row bytes (128 data + 16 pad)
#define TILEB (64 * TRB)              // 9216
#define STAGEB (4 * TILEB)            // 36864 (Khi,Klo,Vhi,Vlo)
#define ASMEM (2 * STAGEB + 512)

__device__ __forceinline__ void load_kv(
    uint32_t sb, int tid, int st, int c, size_t headoff,
    const int* __restrict__ attn_mask, int b)
{
#pragma unroll
    for (int i = 0; i < 8; i++) {
        const int idx = tid + i * 256;       // 0..2047
        const int t = idx >> 9;              // tile 0..3
        const int r = (idx >> 3) & 63;
        const int cc = idx & 7;
        const __nv_bfloat16* base =
            (t == 0) ? g_Khi : (t == 1) ? g_Klo : (t == 2) ? g_Vhi : g_Vlo;
        const __nv_bfloat16* src = base + headoff + (size_t)(c * 64 + r) * DH + cc * 8;
        cp16(sb + st * STAGEB + t * TILEB + r * TRB + cc * 16, src);
    }
    if (tid < 16)
        cp16(sb + 2 * STAGEB + st * 256 + tid * 16, attn_mask + b * SEQ + c * 64 + tid * 4);
    CP_COMMIT();
}

__global__ __launch_bounds__(256, 2)
void attn_mma_kernel(const int* __restrict__ attn_mask)
{
    extern __shared__ char smem[];
    const uint32_t sb = smem_u32(smem);
    const int tid = threadIdx.x;
    const int lane = tid & 31;
    const int wid = tid >> 5;
    const int qb = blockIdx.x;
    const int h = blockIdx.y;
    const int b = blockIdx.z;
    const int q0 = qb * QT;
    const size_t headoff = (size_t)(b * NH + h) * SEQ * DH;

    // ---- stage Q tile (hi/lo) into stage-0 buffer, read frags, then reuse ----
#pragma unroll
    for (int i = 0; i < 8; i++) {
        const int idx = tid + i * 256;       // 0..2047
        const int t = idx >> 10;             // 0 hi, 1 lo
        const int r = (idx >> 3) & 127;
        const int cc = idx & 7;
        const __nv_bfloat16* base = t ? g_Qlo : g_Qhi;
        cp16(sb + t * 18432 + r * TRB + cc * 16,
             base + headoff + (size_t)(q0 + r) * DH + cc * 8);
    }
    CP_COMMIT();
    cp_wait<0>();
    __syncthreads();

    uint32_t qh[4][4], ql[4][4];
    {
        const int arow = wid * 16 + (lane & 15);
#pragma unroll
        for (int ks = 0; ks < 4; ks++) {
            const uint32_t off = (uint32_t)arow * TRB + (ks * 16 + 8 * ((lane >> 4) & 1)) * 2;
            ldsm_x4(qh[ks][0], qh[ks][1], qh[ks][2], qh[ks][3], sb + off);
            ldsm_x4(ql[ks][0], ql[ks][1], ql[ks][2], ql[ks][3], sb + 18432 + off);
        }
    }
    __syncthreads();   // done with Q staging area

    const int r0g = q0 + wid * 16 + (lane >> 2);
    const int r1g = r0g + 8;

    float m0r = -1e4f, m1r = -1e4f, l0 = 0.0f, l1 = 0.0f;
    float o[8][4];
#pragma unroll
    for (int j = 0; j < 8; j++)
#pragma unroll
        for (int v = 0; v < 4; v++) o[j][v] = 0.0f;

    const int clo = (2 * qb >= 8) ? (2 * qb - 8) : 0;
    const int chi = 2 * qb + 1;

    load_kv(sb, tid, 0, clo, headoff, attn_mask, b);

#pragma unroll 1
    for (int c = clo; c <= chi; c++) {
        const int st = (c - clo) & 1;
        if (c < chi) {
            load_kv(sb, tid, st ^ 1, c + 1, headoff, attn_mask, b);
            cp_wait<1>();
        } else {
            cp_wait<0>();
        }
        __syncthreads();

        const uint32_t kb = sb + st * STAGEB;

        // ---- S = Q K^T (3 split terms) ----
        float p[8][4];
#pragma unroll
        for (int j = 0; j < 8; j++)
#pragma unroll
            for (int v = 0; v < 4; v++) p[j][v] = 0.0f;

#pragma unroll
        for (int ks = 0; ks < 4; ks++) {
            uint32_t bh[8][2], bl[8][2];
#pragma unroll
            for (int jj = 0; jj < 4; jj++) {
                const int nrow = 16 * jj + 8 * ((lane >> 4) & 1) + (lane & 7);
                const int kcolb = (ks * 16 + 8 * ((lane >> 3) & 1)) * 2;
                const uint32_t off = (uint32_t)nrow * TRB + kcolb;
                ldsm_x4(bh[jj*2][0], bh[jj*2][1], bh[jj*2+1][0], bh[jj*2+1][1], kb + off);
                ldsm_x4(bl[jj*2][0], bl[jj*2][1], bl[jj*2+1][0], bl[jj*2+1][1], kb + TILEB + off);
            }
#pragma unroll
            for (int j = 0; j < 8; j++) {
                mma16816(p[j], qh[ks], bh[j]);
                mma16816(p[j], qh[ks], bl[j]);
                mma16816(p[j], ql[ks], bh[j]);
            }
        }

        // ---- mask + online softmax ----
        const int* mk = (const int*)(smem + 2 * STAGEB + st * 256);
        const int c64 = c * 64;
#pragma unroll
        for (int j = 0; j < 8; j++) {
            const int kloc = j * 8 + 2 * (lane & 3);
            const int kg = c64 + kloc;
            const int mv0 = mk[kloc], mv1 = mk[kloc + 1];
            if (!(kg     <= r0g && kg     >= r0g - (WIN-1) && mv0)) p[j][0] = -1e30f;
            if (!(kg + 1 <= r0g && kg + 1 >= r0g - (WIN-1) && mv1)) p[j][1] = -1e30f;
            if (!(kg     <= r1g && kg     >= r1g - (WIN-1) && mv0)) p[j][2] = -1e30f;
            if (!(kg + 1 <= r1g && kg + 1 >= r1g - (WIN-1) && mv1)) p[j][3] = -1e30f;
        }
        float mx0 = -1e30f, mx1 = -1e30f;
#pragma unroll
        for (int j = 0; j < 8; j++) {
            mx0 = fmaxf(mx0, fmaxf(p[j][0], p[j][1]));
            mx1 = fmaxf(mx1, fmaxf(p[j][2], p[j][3]));
        }
        mx0 = fmaxf(mx0, __shfl_xor_sync(0xffffffffu, mx0, 1));
        mx0 = fmaxf(mx0, __shfl_xor_sync(0xffffffffu, mx0, 2));
        mx1 = fmaxf(mx1, __shfl_xor_sync(0xffffffffu, mx1, 1));
        mx1 = fmaxf(mx1, __shfl_xor_sync(0xffffffffu, mx1, 2));

        const float mn0 = fmaxf(m0r, mx0);
        const float mn1 = fmaxf(m1r, mx1);
        const float cr0 = __expf(m0r - mn0);
        const float cr1 = __expf(m1r - mn1);
        m0r = mn0; m1r = mn1;
        l0 *= cr0; l1 *= cr1;
#pragma unroll
        for (int j = 0; j < 8; j++) {
            o[j][0] *= cr0; o[j][1] *= cr0;
            o[j][2] *= cr1; o[j][3] *= cr1;
        }
        float s0 = 0.0f, s1 = 0.0f;
#pragma unroll
        for (int j = 0; j < 8; j++) {
            p[j][0] = __expf(p[j][0] - mn0); s0 += p[j][0];
            p[j][1] = __expf(p[j][1] - mn0); s0 += p[j][1];
            p[j][2] = __expf(p[j][2] - mn1); s1 += p[j][2];
            p[j][3] = __expf(p[j][3] - mn1); s1 += p[j][3];
        }
        // quad-reduce the denominator partial sums (O sums over all quad keys)
        s0 += __shfl_xor_sync(0xffffffffu, s0, 1);
        s0 += __shfl_xor_sync(0xffffffffu, s0, 2);
        s1 += __shfl_xor_sync(0xffffffffu, s1, 1);
        s1 += __shfl_xor_sync(0xffffffffu, s1, 2);
        l0 += s0; l1 += s1;

        // ---- O += P V (3 split terms) ----
#pragma unroll
        for (int ks2 = 0; ks2 < 4; ks2++) {
            uint32_t ahp[4], alp[4];
            {
                const float p00 = p[2*ks2][0],   p01 = p[2*ks2][1];
                const float p02 = p[2*ks2][2],   p03 = p[2*ks2][3];
                const float p10 = p[2*ks2+1][0], p11 = p[2*ks2+1][1];
                const float p12 = p[2*ks2+1][2], p13 = p[2*ks2+1][3];
                ahp[0] = bfpack(p00, p01);
                ahp[1] = bfpack(p02, p03);
                ahp[2] = bfpack(p10, p11);
                ahp[3] = bfpack(p12, p13);
                const __nv_bfloat162* hp0 = (const __nv_bfloat162*)&ahp[0];
                const __nv_bfloat162* hp1 = (const __nv_bfloat162*)&ahp[1];
                const __nv_bfloat162* hp2 = (const __nv_bfloat162*)&ahp[2];
                const __nv_bfloat162* hp3 = (const __nv_bfloat162*)&ahp[3];
                alp[0] = bfpack(p00 - __bfloat162float(hp0->x), p01 - __bfloat162float(hp0->y));
                alp[1] = bfpack(p02 - __bfloat162float(hp1->x), p03 - __bfloat162float(hp1->y));
                alp[2] = bfpack(p10 - __bfloat162float(hp2->x), p11 - __bfloat162float(hp2->y));
                alp[3] = bfpack(p12 - __bfloat162float(hp3->x), p13 - __bfloat162float(hp3->y));
            }
            uint32_t bvh[8][2], bvl[8][2];
#pragma unroll
            for (int jj = 0; jj < 4; jj++) {
                const int vrow = 16 * ks2 + (lane & 7) + 8 * ((lane >> 3) & 1);
                const int colb = (2 * jj + (lane >> 4)) * 16;
                const uint32_t off = (uint32_t)vrow * TRB + colb;
                ldsm_x4_t(bvh[jj*2][0], bvh[jj*2][1], bvh[jj*2+1][0], bvh[jj*2+1][1],
                          kb + 2 * TILEB + off);
                ldsm_x4_t(bvl[jj*2][0], bvl[jj*2][1], bvl[jj*2+1][0], bvl[jj*2+1][1],
                          kb + 3 * TILEB + off);
            }
#pragma unroll
            for (int j = 0; j < 8; j++) {
                mma16816(o[j], ahp, bvh[j]);
                mma16816(o[j], ahp, bvl[j]);
                mma16816(o[j], alp, bvh[j]);
            }
        }
        __syncthreads();
    }

    // ---- normalize + write bf16 hi/lo to [token, HID] ----
    const float i0 = 1.0f / fmaxf(l0, 1e-30f);
    const float i1 = 1.0f / fmaxf(l1, 1e-30f);
    const size_t t0 = (size_t)(b * SEQ + r0g) * HID + h * DH;
    const size_t t1 = (size_t)(b * SEQ + r1g) * HID + h * DH;
#pragma unroll
    for (int j = 0; j < 8; j++) {
        const int d = j * 8 + 2 * (lane & 3);
        float a0 = o[j][0] * i0, a1 = o[j][1] * i0;
        float a2 = o[j][2] * i1, a3 = o[j][3] * i1;
        __nv_bfloat16 h0 = __float2bfloat16(a0), h1 = __float2bfloat16(a1);
        __nv_bfloat16 h2 = __float2bfloat16(a2), h3 = __float2bfloat16(a3);
        ushort2 u0, u1, v0, v1;
        u0.x = __bfloat16_as_ushort(h0); u0.y = __bfloat16_as_ushort(h1);
        u1.x = __bfloat16_as_ushort(h2); u1.y = __bfloat16_as_ushort(h3);
        v0.x = __bfloat16_as_ushort(__float2bfloat16(a0 - __bfloat162float(h0)));
        v0.y = __bfloat16_as_ushort(__float2bfloat16(a1 - __bfloat162float(h1)));
        v1.x = __bfloat16_as_ushort(__float2bfloat16(a2 - __bfloat162float(h2)));
        v1.y = __bfloat16_as_ushort(__float2bfloat16(a3 - __bfloat162float(h3)));
        *(ushort2*)(g_Ahi + t0 + d) = u0;
        *(ushort2*)(g_Ahi + t1 + d) = u1;
        *(ushort2*)(g_Alo + t0 + d) = v0;
        *(ushort2*)(g_Alo + t1 + d) = v1;
    }
}

// ---------------------------------------------------------------------------
// Launch
// ---------------------------------------------------------------------------
extern "C" void kernel_launch(void* const* d_in, const int* in_sizes, int n_in,
                              void* d_out, int out_size)
{
    const float* x    = (const float*)d_in[0];
    const int*   mask = (const int*)  d_in[1];
    const float* Wq   = (const float*)d_in[2];
    const float* Wk   = (const float*)d_in[3];
    const float* Wv   = (const float*)d_in[4];
    const float* Wo   = (const float*)d_in[5];
    float* out = (float*)d_out;

    static bool attr_set = false;
    if (!attr_set) {
        cudaFuncSetAttribute(qkv_mma_kernel,   cudaFuncAttributeMaxDynamicSharedMemorySize, GSMEM);
        cudaFuncSetAttribute(oproj_mma_kernel, cudaFuncAttributeMaxDynamicSharedMemorySize, GSMEM);
        cudaFuncSetAttribute(attn_mma_kernel,  cudaFuncAttributeMaxDynamicSharedMemorySize, ASMEM);
        attr_set = true;
    }

    split_kernel<<<12288, 256>>>(x, Wq, Wk, Wv, Wo);

    dim3 qgrid(MTOT / BM, HID / BN, 3);
    qkv_mma_kernel<<<qgrid, 256, GSMEM>>>();

    dim3 agrid(SEQ / QT, NH, BATCH);
    attn_mma_kernel<<<agrid, 256, ASMEM>>>(mask);

    dim3 ogrid(MTOT / BM, HID / BN, 1);
    oproj_mma_kernel<<<ogrid, 256, GSMEM>>>(out);
}